// round 1
// baseline (speedup 1.0000x reference)
#include <cuda_runtime.h>
#include <cuda_bf16.h>

#define DF 1024
#define NH 16
#define DH 64
#define BB 2
#define SS 2048
#define MROWS (BB*SS)

// Scratch: Q/K/V projections + attention output (pre output-proj).
__device__ float g_Qf[MROWS * DF];
__device__ float g_Kf[MROWS * DF];
__device__ float g_Vf[MROWS * DF];
__device__ float g_Xc[MROWS * DF];

// ---------------------------------------------------------------------------
// GEMM: C[M,N] = A[M,K] @ W[N,K]^T + bias[N]
// M=4096, N=K=1024. Both A and W are K-major (row-major along K) -> NT GEMM.
// 64x64 tile, BK=16, 256 threads, 4x4 micro-tile per thread. fp32 FFMA.
// ---------------------------------------------------------------------------
__global__ __launch_bounds__(256) void gemm_nt_bias(
    const float* __restrict__ A, const float* __restrict__ W,
    const float* __restrict__ bias, float* __restrict__ C)
{
    const int BM = 64, BN = 64, BK = 16;
    __shared__ float As[BK][BM + 4];
    __shared__ float Ws[BK][BN + 4];

    const int tid = threadIdx.x;
    const int tx = tid & 15;        // 0..15  (N direction)
    const int ty = tid >> 4;        // 0..15  (M direction)
    const int m0 = blockIdx.y * BM;
    const int n0 = blockIdx.x * BN;

    // cooperative load indices: each thread loads one float4 of A and W
    const int lr = tid >> 2;            // 0..63 row within tile
    const int lc = (tid & 3) << 2;      // 0,4,8,12 k within tile

    float acc[4][4] = {};

    for (int k0 = 0; k0 < DF; k0 += BK) {
        float4 av = *reinterpret_cast<const float4*>(A + (size_t)(m0 + lr) * DF + k0 + lc);
        float4 wv = *reinterpret_cast<const float4*>(W + (size_t)(n0 + lr) * DF + k0 + lc);
        As[lc + 0][lr] = av.x; As[lc + 1][lr] = av.y;
        As[lc + 2][lr] = av.z; As[lc + 3][lr] = av.w;
        Ws[lc + 0][lr] = wv.x; Ws[lc + 1][lr] = wv.y;
        Ws[lc + 2][lr] = wv.z; Ws[lc + 3][lr] = wv.w;
        __syncthreads();

        #pragma unroll
        for (int kk = 0; kk < BK; kk++) {
            float4 a4 = *reinterpret_cast<const float4*>(&As[kk][ty << 2]);
            float4 w4 = *reinterpret_cast<const float4*>(&Ws[kk][tx << 2]);
            float a[4] = {a4.x, a4.y, a4.z, a4.w};
            float w[4] = {w4.x, w4.y, w4.z, w4.w};
            #pragma unroll
            for (int i = 0; i < 4; i++)
                #pragma unroll
                for (int j = 0; j < 4; j++)
                    acc[i][j] += a[i] * w[j];
        }
        __syncthreads();
    }

    #pragma unroll
    for (int i = 0; i < 4; i++) {
        int m = m0 + (ty << 2) + i;
        #pragma unroll
        for (int j = 0; j < 4; j++) {
            int n = n0 + (tx << 2) + j;
            C[(size_t)m * DF + n] = acc[i][j] + bias[n];
        }
    }
}

// ---------------------------------------------------------------------------
// Flash-style attention. One thread per query row; block = 256 queries for
// one (batch, head). Online softmax with deferred rescale (rescale o[] only
// when the running max actually increases -> o-update is 1 FMA/elem).
// Scores match the reference exactly: masked keys get score = -1e9.
// Scale = 1/sqrt(D_FEAT) = 1/32 (reference quirk: d_feat, not d_head).
// ---------------------------------------------------------------------------
__global__ __launch_bounds__(256) void attn_kernel(
    const float* __restrict__ Qf, const float* __restrict__ Kf,
    const float* __restrict__ Vf, const int* __restrict__ mask,
    float* __restrict__ Xc)
{
    const int b = blockIdx.z;
    const int h = blockIdx.y;
    const int q = blockIdx.x * 256 + threadIdx.x;

    __shared__ float Ks[64][64];
    __shared__ float Vs[64][64];
    __shared__ float mk[64];

    float qv[DH], o[DH];
    const float* qrow = Qf + ((size_t)(b * SS + q)) * DF + h * DH;
    #pragma unroll
    for (int i = 0; i < DH / 4; i++) {
        float4 v = reinterpret_cast<const float4*>(qrow)[i];
        qv[4*i] = v.x; qv[4*i+1] = v.y; qv[4*i+2] = v.z; qv[4*i+3] = v.w;
    }
    #pragma unroll
    for (int i = 0; i < DH; i++) o[i] = 0.f;

    float m = -1e30f, l = 0.f;

    const int lr = threadIdx.x >> 2;          // 0..63
    const int lc = (threadIdx.x & 3) << 4;    // 0,16,32,48

    for (int kt = 0; kt < SS; kt += 64) {
        __syncthreads();
        const float* kr = Kf + ((size_t)(b * SS + kt + lr)) * DF + h * DH + lc;
        const float* vr = Vf + ((size_t)(b * SS + kt + lr)) * DF + h * DH + lc;
        #pragma unroll
        for (int j = 0; j < 16; j += 4) {
            float4 kv = *reinterpret_cast<const float4*>(kr + j);
            float4 vv = *reinterpret_cast<const float4*>(vr + j);
            *reinterpret_cast<float4*>(&Ks[lr][lc + j]) = kv;
            *reinterpret_cast<float4*>(&Vs[lr][lc + j]) = vv;
        }
        if (threadIdx.x < 64)
            mk[threadIdx.x] = (mask[b * SS + kt + threadIdx.x] == 0) ? 1.f : 0.f;
        __syncthreads();

        for (int k = 0; k < 64; k++) {
            // q . K[k]  (broadcast LDS.128, 4 partial accumulators)
            float d0 = 0.f, d1 = 0.f, d2 = 0.f, d3 = 0.f;
            const float4* krow4 = reinterpret_cast<const float4*>(&Ks[k][0]);
            #pragma unroll
            for (int i = 0; i < 16; i++) {
                float4 kv = krow4[i];
                d0 += qv[4*i]   * kv.x;
                d1 += qv[4*i+1] * kv.y;
                d2 += qv[4*i+2] * kv.z;
                d3 += qv[4*i+3] * kv.w;
            }
            float s = ((d0 + d1) + (d2 + d3)) * 0.03125f;
            if (mk[k] != 0.f) s = -1e9f;

            if (s > m) {                       // deferred rescale (rare)
                float c = __expf(m - s);
                l *= c;
                #pragma unroll
                for (int i = 0; i < DH; i++) o[i] *= c;
                m = s;
            }
            float p = __expf(s - m);
            l += p;

            const float4* vrow4 = reinterpret_cast<const float4*>(&Vs[k][0]);
            #pragma unroll
            for (int i = 0; i < 16; i++) {
                float4 vv = vrow4[i];
                o[4*i]   += p * vv.x;
                o[4*i+1] += p * vv.y;
                o[4*i+2] += p * vv.z;
                o[4*i+3] += p * vv.w;
            }
        }
    }

    float inv = 1.f / l;
    float* xr = Xc + ((size_t)(b * SS + q)) * DF + h * DH;
    #pragma unroll
    for (int i = 0; i < DH / 4; i++) {
        float4 v = {o[4*i] * inv, o[4*i+1] * inv, o[4*i+2] * inv, o[4*i+3] * inv};
        reinterpret_cast<float4*>(xr)[i] = v;
    }
}

// ---------------------------------------------------------------------------
// launch
// ---------------------------------------------------------------------------
extern "C" void kernel_launch(void* const* d_in, const int* in_sizes, int n_in,
                              void* d_out, int out_size)
{
    const float* Q    = (const float*)d_in[0];
    const float* K    = (const float*)d_in[1];
    const float* V    = (const float*)d_in[2];
    const int*   mask = (const int*)  d_in[3];
    const float* Wq   = (const float*)d_in[4];
    const float* bq   = (const float*)d_in[5];
    const float* Wk   = (const float*)d_in[6];
    const float* bk   = (const float*)d_in[7];
    const float* Wv   = (const float*)d_in[8];
    const float* bv   = (const float*)d_in[9];
    const float* Wo   = (const float*)d_in[10];
    const float* bo   = (const float*)d_in[11];
    float* out = (float*)d_out;

    float *Qf, *Kf, *Vf, *Xc;
    cudaGetSymbolAddress((void**)&Qf, g_Qf);
    cudaGetSymbolAddress((void**)&Kf, g_Kf);
    cudaGetSymbolAddress((void**)&Vf, g_Vf);
    cudaGetSymbolAddress((void**)&Xc, g_Xc);

    dim3 ggrid(DF / 64, MROWS / 64);   // (16, 64)
    dim3 gblk(256);

    gemm_nt_bias<<<ggrid, gblk>>>(Q, Wq, bq, Qf);
    gemm_nt_bias<<<ggrid, gblk>>>(K, Wk, bk, Kf);
    gemm_nt_bias<<<ggrid, gblk>>>(V, Wv, bv, Vf);

    attn_kernel<<<dim3(SS / 256, NH, BB), 256>>>(Qf, Kf, Vf, mask, Xc);

    gemm_nt_bias<<<ggrid, gblk>>>(Xc, Wo, bo, out);
}